// round 2
// baseline (speedup 1.0000x reference)
#include <cuda_runtime.h>
#include <cstdint>

typedef unsigned long long ull;

#define NROWS 147584   // K_SIZE + B_SIZE
#define KSIZE 147456
#define LATD  512
#define NB    16
#define NFIN  128
#define NFOUT 128
#define HH    64
#define WW    64

// scratch for generated kernels+bias: 16 * 147584 * 4B = 9.45 MB
__device__ float g_ks[NB * NROWS];

// pack two f32 into a 64-bit reg (ALU pipe, dual-issues vs FMA pipe)
#define PK2(dst, a, b) \
  asm("mov.b64 %0, {%1, %2};" : "=l"(dst) : "r"(__float_as_uint(a)), "r"(__float_as_uint(b)))
// packed fp32x2 FMA (FFMA2): 2 FMA per instr, restores 128 FMA/cyc/SM
#define FMA2(acc, a, b) \
  asm("fma.rn.f32x2 %0, %1, %2, %3;" : "=l"(acc) : "l"(a), "l"(b), "l"(acc))

// ---------------------------------------------------------------------------
// Kernel A: ks[b][j] = sum_k lat[b][k] * W[j][k] + bias[j]
// 256 rows per block, row-per-thread. W staged in smem (pad-33 stride ->
// conflict-free compute reads, bank == (t+k) mod 32). lat chunk transposed to
// [k][b] so the 16 batch values per k are 4x LDS128 broadcasts (8 f32x2).
// HBM-bound on W (302 MB). Batches packed in f32x2 pairs.
// ---------------------------------------------------------------------------
#define TJ 256
#define KC 32

__global__ __launch_bounds__(256, 4) void hyper_gemm(
    const float* __restrict__ lat, const float* __restrict__ Wm,
    const float* __restrict__ bias)
{
  __shared__ float Ws[TJ * (KC + 1)];               // [r][k], stride 33
  __shared__ __align__(16) float latc[KC * 16];     // [k][b]
  const int tid = threadIdx.x;
  const int j0 = blockIdx.x * TJ;
  const int j = j0 + tid;

  ull acc[8];
#pragma unroll
  for (int i = 0; i < 8; i++) acc[i] = 0ull;

  for (int kc = 0; kc < LATD; kc += KC) {
    __syncthreads();
    // stage W chunk: rows j0..j0+255, cols kc..kc+KC-1 (coalesced float4 reads)
    {
      const float4* Wg = reinterpret_cast<const float4*>(Wm);
#pragma unroll
      for (int p = 0; p < (TJ * KC / 4) / 256; p++) {   // 8 passes
        int idx4 = p * 256 + tid;
        int r  = idx4 >> 3;      // row within tile
        int kq = idx4 & 7;       // float4 within row chunk
        int jr = j0 + r;
        float4 v = make_float4(0.f, 0.f, 0.f, 0.f);
        if (jr < NROWS) v = Wg[jr * (LATD / 4) + (kc >> 2) + kq];
        float* dst = &Ws[r * (KC + 1) + kq * 4];
        dst[0] = v.x; dst[1] = v.y; dst[2] = v.z; dst[3] = v.w;
      }
    }
    // stage lat chunk transposed: latc[k][b]  (tiny; lat stays L2-resident)
    for (int idx = tid; idx < KC * 16; idx += 256) {
      int kl = idx >> 4;
      int bb = idx & 15;
      latc[kl * 16 + bb] = lat[bb * LATD + kc + kl];
    }
    __syncthreads();

    const ulonglong2* latp = reinterpret_cast<const ulonglong2*>(latc);
#pragma unroll
    for (int k = 0; k < KC; k++) {
      float wv = Ws[tid * (KC + 1) + k];
      ull w2; PK2(w2, wv, wv);
#pragma unroll
      for (int q = 0; q < 4; q++) {
        ulonglong2 lv = latp[k * 4 + q];   // 4 batch-pairs per LDS128 broadcast
        FMA2(acc[2 * q + 0], w2, lv.x);
        FMA2(acc[2 * q + 1], w2, lv.y);
      }
    }
  }

  if (j < NROWS) {
    float bv = bias[j];
#pragma unroll
    for (int p = 0; p < 8; p++) {
      float2 v = *reinterpret_cast<float2*>(&acc[p]);
      g_ks[(2 * p + 0) * NROWS + j] = v.x + bv;
      g_ks[(2 * p + 1) * NROWS + j] = v.y + bv;
    }
  }
}

// ---------------------------------------------------------------------------
// Kernel B: per-sample 3x3 conv with generated kernels, all in f32x2.
// Block(256) covers: b fixed, 32 fout x 4 rows x 64 cols.
//   warp w: row = w&3, fout-half = w>>2 (16 fouts each)
//   lane l: cols {l, l+32}  -> consecutive-lane smem reads, conflict-free
// acc: 8 fout-pairs (f32x2) x 2 cols = 16 ull accumulators.
// FIN chunked by 16: ws[tap][fo] (stride 36, 16B-aligned broadcasts),
// xs[fi][6 rows][68] with halo+pad.
// ---------------------------------------------------------------------------
#define FC 16

__global__ __launch_bounds__(256, 2) void dyn_conv(
    const float* __restrict__ x, float* __restrict__ out)
{
  __shared__ __align__(16) float ws[FC * 9 * 36];   // [r=fi*9+tap][fo], 20.25 KB
  __shared__ float xs[FC * 6 * 68];                 // [fi][rr][cx], 25.5 KB
  const int tid  = threadIdx.x;
  const int lane = tid & 31;
  const int wrp  = tid >> 5;
  const int row  = wrp & 3;      // output row within tile
  const int foh  = wrp >> 2;     // 0/1 -> which 16-fout half
  const int b    = blockIdx.z;
  const int fog  = blockIdx.y;   // fout group of 32
  const int rt   = blockIdx.x;   // row tile (4 rows)
  const int grow0 = rt * 4 - 1;

  ull acc[16];
#pragma unroll
  for (int i = 0; i < 16; i++) acc[i] = 0ull;

  const float* kbase = g_ks + b * NROWS + fog * 32 * 1152;
  const float* xbase = x + (b * NFIN) * (HH * WW);

  for (int fc = 0; fc < NFIN; fc += FC) {
    __syncthreads();
    // stage weights: 32 fouts x FC fins x 9 taps  (contiguous 144-float runs)
    for (int idx = tid; idx < 32 * FC * 9; idx += 256) {
      int fo = idx / (FC * 9);
      int r  = idx - fo * (FC * 9);       // fi*9 + tap
      ws[r * 36 + fo] = kbase[fo * 1152 + fc * 9 + r];
    }
    // stage x tile with halo: rows grow0..grow0+5, cols -1..64
    for (int idx = tid; idx < FC * 6 * 66; idx += 256) {
      int fi  = idx / 396;
      int rem = idx - fi * 396;
      int rr  = rem / 66;
      int cx  = rem - rr * 66;
      int gr  = grow0 + rr;
      int gc  = cx - 1;
      float v = 0.f;
      if ((unsigned)gr < (unsigned)HH && (unsigned)gc < (unsigned)WW)
        v = xbase[(fc + fi) * (HH * WW) + gr * WW + gc];
      xs[fi * 408 + rr * 68 + cx] = v;
    }
    __syncthreads();

#pragma unroll 2
    for (int fi = 0; fi < FC; fi++) {
      const float* xrow0 = &xs[fi * 408];
      const float* wsb   = &ws[fi * 9 * 36 + foh * 16];
#pragma unroll
      for (int kh = 0; kh < 3; kh++) {
        const float* xr = xrow0 + (row + kh) * 68 + lane;
        float xa0 = xr[0],  xa1 = xr[1],  xa2 = xr[2];
        float xb0 = xr[32], xb1 = xr[33], xb2 = xr[34];
        ull xpa[3], xpb[3];
        PK2(xpa[0], xa0, xa0); PK2(xpa[1], xa1, xa1); PK2(xpa[2], xa2, xa2);
        PK2(xpb[0], xb0, xb0); PK2(xpb[1], xb1, xb1); PK2(xpb[2], xb2, xb2);
#pragma unroll
        for (int kw = 0; kw < 3; kw++) {
          const float4* wq = reinterpret_cast<const float4*>(wsb + (kh * 3 + kw) * 36);
          float4 wA = wq[0], wB = wq[1], wC = wq[2], wD = wq[3];  // 16 fouts
          ull w2[8];
          PK2(w2[0], wA.x, wA.y); PK2(w2[1], wA.z, wA.w);
          PK2(w2[2], wB.x, wB.y); PK2(w2[3], wB.z, wB.w);
          PK2(w2[4], wC.x, wC.y); PK2(w2[5], wC.z, wC.w);
          PK2(w2[6], wD.x, wD.y); PK2(w2[7], wD.z, wD.w);
#pragma unroll
          for (int p = 0; p < 8; p++) {
            FMA2(acc[2 * p + 0], w2[p], xpa[kw]);   // col = lane
            FMA2(acc[2 * p + 1], w2[p], xpb[kw]);   // col = lane + 32
          }
        }
      }
    }
  }

  // epilogue: add bias, store (coalesced per fout row)
  const int gr  = rt * 4 + row;
  const int fo0 = fog * 32 + foh * 16;
  const int obase = (b * NFOUT) * (HH * WW);
  const float* biasb = g_ks + b * NROWS + KSIZE;
#pragma unroll
  for (int p = 0; p < 8; p++) {
    float2 v0 = *reinterpret_cast<float2*>(&acc[2 * p + 0]);
    float2 v1 = *reinterpret_cast<float2*>(&acc[2 * p + 1]);
    int foA = fo0 + 2 * p;
    int foB = foA + 1;
    float bA = biasb[foA];
    float bB = biasb[foB];
    out[obase + foA * (HH * WW) + gr * WW + lane]      = v0.x + bA;
    out[obase + foA * (HH * WW) + gr * WW + lane + 32] = v1.x + bA;
    out[obase + foB * (HH * WW) + gr * WW + lane]      = v0.y + bB;
    out[obase + foB * (HH * WW) + gr * WW + lane + 32] = v1.y + bB;
  }
}

// ---------------------------------------------------------------------------
extern "C" void kernel_launch(void* const* d_in, const int* in_sizes, int n_in,
                              void* d_out, int out_size) {
  const float* x   = (const float*)d_in[0];   // [16,128,64,64]
  const float* lat = (const float*)d_in[1];   // [16,512]
  const float* Wm  = (const float*)d_in[2];   // [147584,512]
  const float* bv  = (const float*)d_in[3];   // [147584]
  float* out = (float*)d_out;                 // [16,128,64,64]

  hyper_gemm<<<(NROWS + TJ - 1) / TJ, 256>>>(lat, Wm, bv);

  dim3 g(HH / 4, NFOUT / 32, NB);             // 16 x 4 x 16 = 1024 blocks
  dyn_conv<<<g, 256>>>(x, out);
}